// round 14
// baseline (speedup 1.0000x reference)
#include <cuda_runtime.h>
#include <cuda_fp16.h>
#include <math.h>

#ifndef M_PI
#define M_PI 3.14159265358979323846
#endif

// FOUR z-slices per sample via TWO half2 tiles (4-byte elements, TS=263
// conflict-clean stride): tileA = half2(z0,z1), tileB = half2(z2,z3).
// LANE = Y-LINE layout (round 13): warp = (view, 32 consecutive y); x is a
// uniform scalar loop over the warp's union range.
// 4 y-band phases (round-10 geometry): band p tile holds vol rows
// (64p-4 .. 64p+67) clamped, at trow = volrow - (64p-4) + 2; rows 0,1 and
// tail rows zero. trow(floor) = floor(iy) - (64p-6), clamp [0,74].
// Ownership: band p owns floor(iy) in [64p, 64p+63] (band0 extends down,
// band3 up) -> kill predicate trow in [klo,khi]:
//   band0 [0,69], band1/2 [6,69], band3 [6,74].
// Ranges from iy=64k crossings with -2/+3 margins (round-13 consistency fix).
#define TS    263
#define TROWS 76
#define TOFF  (TROWS * TS)
#define TILE_BYTES (2 * TROWS * TS * 4)

typedef unsigned long long ull;
typedef unsigned int uint;

#define FMA2(d,a,b,c) asm("fma.rn.f32x2 %0, %1, %2, %3;" : "=l"(d) : "l"(a), "l"(b), "l"(c))
#define ADD2(d,a,b)   asm("add.rn.f32x2 %0, %1, %2;"     : "=l"(d) : "l"(a), "l"(b))
#define PK2(d,lo,hi)  asm("mov.b64 %0, {%1, %2};"        : "=l"(d) : "f"(lo), "f"(hi))
#define UNPK2(lo,hi,v) asm("mov.b64 {%0, %1}, %2;"       : "=f"(lo), "=f"(hi) : "l"(v))
// fp16x2. PTX cvt.rn.f16x2.f32 d, a, b : a -> HIGH half, b -> LOW half.
#define HSUB2(d,a,b)   asm("sub.rn.f16x2 %0, %1, %2;"     : "=r"(d) : "r"(a), "r"(b))
#define HFMA2(d,a,b,c) asm("fma.rn.f16x2 %0, %1, %2, %3;" : "=r"(d) : "r"(a), "r"(b), "r"(c))
#define BCASTH(d,f)    asm("cvt.rn.f16x2.f32 %0, %1, %2;" : "=r"(d) : "f"(f), "f"(f))
#define PACKH(d,lo,hi) asm("cvt.rn.f16x2.f32 %0, %1, %2;" : "=r"(d) : "f"(hi), "f"(lo))
// half2 -> packed f32x2 (ull)
#define H2P2(d,v)      asm("{.reg .b16 l,h; .reg .f32 fl,fh; mov.b32 {l,h}, %1; " \
                           "cvt.f32.f16 fl, l; cvt.f32.f16 fh, h; mov.b64 %0, {fl, fh};}" \
                           : "=l"(d) : "r"(v))

__device__ int2 g_xrng[512];   // [p*128 + v*8 + yblk] = union {xmin, xmax}

__global__ void fp_zero_kernel(float4* __restrict__ out, int n4) {
    int i = blockIdx.x * blockDim.x + threadIdx.x;
    if (i < n4) out[i] = make_float4(0.f, 0.f, 0.f, 0.f);
}

// Per (band, view, y-block of 32): union of per-line active x ranges.
__global__ void fp_range_kernel() {
    int t = blockIdx.x * 256 + threadIdx.x;   // 0..511
    int p = t >> 7, v = (t >> 3) & 15, blk = t & 7;
    float unit = (float)(M_PI / 16.0);
    float mu   = (float)(M_PI / 180.0);
    float a = __fadd_rn(mu, __fmul_rn((float)v, unit));
    double da = (double)a;
    float c = (float)cos(da), s = (float)sin(da);   // s > 0 all views
    float inv_s = __fdividef(1.f, s);
    float inv_c = __fdividef(1.f, c);
    int mn = 256, mx = 0;
    for (int k = 0; k < 32; k++) {
        int y = (blk << 5) + k;
        float yf = (float)y - 127.5f;
        float A = fmaf(-s, yf, fmaf(-c, 127.5f, 127.5f));
        float B = fmaf( c, yf, fmaf(-s, 127.5f, 127.5f));
        float xa = (-1.f  - B) * inv_s;
        float xb = (256.f - B) * inv_s;
        float e0 = (-2.f  - A) * inv_c;
        float e1 = (258.f - A) * inv_c;
        float lo = fmaxf(xa, fminf(e0, e1));
        float hi = fminf(xb, fmaxf(e0, e1));
        int xlo = max(0,   (int)floorf(lo) - 2);
        int xhi = min(256, (int)ceilf(hi) + 3);
        if (xhi < xlo) xhi = xlo;
        int xbeg = xlo, xend = xhi;
        if (p > 0) {   // lower boundary: iy = 64p crossing
            float tb = (64.f * (float)p - B) * inv_s;
            tb = fminf(fmaxf(tb, -100000.f), 100000.f);
            xbeg = max(xlo, (int)floorf(tb) + 1 - 2);
        }
        if (p < 3) {   // upper boundary: iy = 64(p+1) crossing
            float tb = (64.f * (float)(p + 1) - B) * inv_s;
            tb = fminf(fmaxf(tb, -100000.f), 100000.f);
            xend = min(xhi, (int)floorf(tb) + 1 + 3);
        }
        if (xbeg < xend) { mn = min(mn, xbeg); mx = max(mx, xend); }
    }
    if (mn >= mx) { mn = 0; mx = 0; }
    g_xrng[t] = make_int2(mn, mx);
}

extern __shared__ uint tile[];   // [0,TOFF) = tileA (z0,z1); [TOFF,2*TOFF) = tileB

__global__ void __launch_bounds__(1024, 1)
fp_main_kernel(const float* __restrict__ vol, float* __restrict__ out)
{
    const int bx  = blockIdx.x;
    const int zq  = bx >> 4;          // z-quad 0..63
    const int p   = (bx >> 2) & 3;    // y-band phase
    const int vg  = bx & 3;           // view group of 4
    const int tid = threadIdx.x;

    __shared__ float s_c[16], s_s[16], s_Ac[16], s_Bc[16];
    if (tid < 16) {
        float unit = (float)(M_PI / 16.0);
        float mu   = (float)(M_PI / 180.0);
        float a = __fadd_rn(mu, __fmul_rn((float)tid, unit));
        double da = (double)a;
        float c = (float)cos(da), s = (float)sin(da);
        s_c[tid] = c; s_s[tid] = s;
        s_Ac[tid] = fmaf(-c, 127.5f, 127.5f);
        s_Bc[tid] = fmaf(-s, 127.5f, 127.5f);
    }

    // zero both tiles, then overlay data rows
    for (int i = tid; i < 2 * TOFF; i += 1024) tile[i] = 0u;
    __syncthreads();

    const int vstart = 64 * p - 4;
    const int r0 = max(0, vstart);
    const int r1 = min(255, vstart + 71);
    const int nrows = r1 - r0 + 1;
    const int rowoff = r0 - vstart + 2;            // tile row of vol row r0
    const float* __restrict__ v0 = vol + ((size_t)(zq << 2) << 16) + (r0 << 8);
    const float* __restrict__ v1 = v0 + 65536;
    const float* __restrict__ v2 = v0 + 2 * 65536;
    const float* __restrict__ v3 = v0 + 3 * 65536;
    for (int i = tid; i < nrows * 64; i += 1024) {
        int r = i >> 6, c4 = (i & 63) << 2;
        int off = (r << 8) + c4;
        float4 a = *(const float4*)(v0 + off);
        float4 b = *(const float4*)(v1 + off);
        float4 c = *(const float4*)(v2 + off);
        float4 d = *(const float4*)(v3 + off);
        uint* dA = &tile[(r + rowoff) * TS + 2 + c4];
        uint* dB = dA + TOFF;
        uint t;
        PACKH(t, a.x, b.x); dA[0] = t;  PACKH(t, c.x, d.x); dB[0] = t;
        PACKH(t, a.y, b.y); dA[1] = t;  PACKH(t, c.y, d.y); dB[1] = t;
        PACKH(t, a.z, b.z); dA[2] = t;  PACKH(t, c.z, d.z); dB[2] = t;
        PACKH(t, a.w, b.w); dA[3] = t;  PACKH(t, c.w, d.w); dB[3] = t;
    }
    __syncthreads();

    const int warp = tid >> 5, lane = tid & 31;
    const int v    = (vg << 2) + (warp >> 3);
    const int yblk = warp & 7;
    const int y    = (yblk << 5) + lane;

    // bit-domain clamps: tcol in [0,259], trow in [0,74]
    const int      LO_MIN = 0x4B400000 - 2,          LO_MAX = LO_MIN + 259;
    const int      HI_MIN = 0x4B400000 + 64 * p - 6, HI_MAX = HI_MIN + 74;
    const unsigned UOFF   = (unsigned)HI_MIN * (unsigned)TS + (unsigned)LO_MIN;
    // ownership kill: trow in [klo,khi]
    const int      klo = (p == 0) ? 0 : 6;
    const int      khi = (p == 3) ? 74 : 69;
    const int      KB = HI_MIN + klo;
    const unsigned KS = (unsigned)(khi - klo);

    const ull MAGIC2  = 0x4B4000004B400000ULL;
    const ull NMAGIC2 = 0xCB400000CB400000ULL;
    const ull HALF2C  = 0x3F0000003F000000ULL;
    const ull NONE2   = 0xBF800000BF800000ULL;
    const ull STEP1   = 0x3F8000003F800000ULL;  // (1, 1)

    const float c = s_c[v], s = s_s[v];
    const float yf = (float)y - 127.5f;
    const float A = fmaf(-s, yf, s_Ac[v]) - 0.5f;
    const float B = fmaf( c, yf, s_Bc[v]) - 0.5f;
    ull cs2, ab2;
    PK2(cs2, c, s);
    PK2(ab2, A, B);

    int2 rng = __ldg(&g_xrng[(p << 7) + (v << 3) + yblk]);
    const int xmin = rng.x, xmax = rng.y;
    if (xmin >= xmax) return;

    ull xf2, accP0 = 0ULL, accP1 = 0ULL;
    const float xm = (float)xmin;
    PK2(xf2, xm, xm);

    #pragma unroll 2
    for (int x = xmin; x < xmax; x++) {
        ull ih2, m2, f2, wh2, w2;
        FMA2(ih2, cs2, xf2, ab2);      // (ix-.5, iy-.5)
        ADD2(m2,  ih2, MAGIC2);
        ADD2(f2,  m2,  NMAGIC2);       // (floor ix, floor iy)
        FMA2(wh2, f2,  NONE2, ih2);
        ADD2(w2,  wh2, HALF2C);        // (wx, wy)
        int blo = (int)(unsigned)m2;
        int bhi = (int)(unsigned)(m2 >> 32);
        bool ok = ((unsigned)(bhi - KB) <= KS);    // ownership kill
        blo = min(max(blo, LO_MIN), LO_MAX);
        bhi = min(max(bhi, HI_MIN), HI_MAX);
        unsigned idx = (unsigned)bhi * (unsigned)TS + (unsigned)blo - UOFF;
        const uint* tA = &tile[idx];
        const uint* tB = tA + TOFF;
        uint A00 = tA[0], A01 = tA[1], A10 = tA[TS], A11 = tA[TS + 1];
        uint B00 = tB[0], B01 = tB[1], B10 = tB[TS], B11 = tB[TS + 1];
        float wx = __uint_as_float((unsigned)w2);
        float wy = __uint_as_float((unsigned)(w2 >> 32));
        uint WX, WY; BCASTH(WX, wx); BCASTH(WY, wy);
        uint D0, D1, H0, H1, DH, VALa, VALb;
        HSUB2(D0, A01, A00);
        HSUB2(D1, A11, A10);
        HFMA2(H0, WX, D0, A00);
        HFMA2(H1, WX, D1, A10);
        HSUB2(DH, H1, H0);
        HFMA2(VALa, WY, DH, H0);
        HSUB2(D0, B01, B00);
        HSUB2(D1, B11, B10);
        HFMA2(H0, WX, D0, B00);
        HFMA2(H1, WX, D1, B10);
        HSUB2(DH, H1, H0);
        HFMA2(VALb, WY, DH, H0);
        VALa = ok ? VALa : 0u;
        VALb = ok ? VALb : 0u;
        ull pa, pb;
        H2P2(pa, VALa); H2P2(pb, VALb);
        ADD2(accP0, accP0, pa);
        ADD2(accP1, accP1, pb);
        ADD2(xf2, xf2, STEP1);
    }

    float a0, a1, a2, a3;
    UNPK2(a0, a1, accP0);
    UNPK2(a2, a3, accP1);
    int oidx = ((((zq << 2) << 8) + y) << 4) + v;
    atomicAdd(&out[oidx],            a0);
    atomicAdd(&out[oidx +     4096], a1);
    atomicAdd(&out[oidx + 2 * 4096], a2);
    atomicAdd(&out[oidx + 3 * 4096], a3);
}

extern "C" void kernel_launch(void* const* d_in, const int* in_sizes, int n_in,
                              void* d_out, int out_size) {
    (void)in_sizes; (void)n_in;
    cudaFuncSetAttribute(fp_main_kernel,
                         cudaFuncAttributeMaxDynamicSharedMemorySize, TILE_BYTES);
    fp_zero_kernel<<<512, 512>>>((float4*)d_out, out_size / 4);
    fp_range_kernel<<<2, 256>>>();
    fp_main_kernel<<<1024, 1024, TILE_BYTES>>>((const float*)d_in[0], (float*)d_out);
}

// round 15
// speedup vs baseline: 1.0045x; 1.0045x over previous
#include <cuda_runtime.h>
#include <cuda_fp16.h>
#include <math.h>

#ifndef M_PI
#define M_PI 3.14159265358979323846
#endif

// FOUR z-slices per sample via TWO half2 tiles (4-byte elements, TS=263
// conflict-clean): tileA = half2(z0,z1), tileB = half2(z2,z3).
// LANE = Y-LINE (round 13) + THREE 85-row y-bands (boundaries iy=85,170):
//   band b loads vol rows 85b..85b+85 (86 rows) at trow 4..89; trows 0..3
//   and 90..94 zero. trow = floor(iy) - 85b + 4, clamp [0,93].
//   Ownership: b0 floors <=84 (trow<=88, klo=0), b1 85..169 (trow 4..88),
//   b2 >=170 (trow 4..93; rows>=90 are zero). Kill = one unsigned window.
// Warp = (view-of-2, yblk-of-8, x-half): 32 warps/CTA; grid (24=3band*8vg, 64zq).
#define TS    263
#define TROWS 95
#define TOFF  (TROWS * TS)
#define TILE_BYTES (2 * TROWS * TS * 4)

typedef unsigned long long ull;
typedef unsigned int uint;

#define FMA2(d,a,b,c) asm("fma.rn.f32x2 %0, %1, %2, %3;" : "=l"(d) : "l"(a), "l"(b), "l"(c))
#define ADD2(d,a,b)   asm("add.rn.f32x2 %0, %1, %2;"     : "=l"(d) : "l"(a), "l"(b))
#define PK2(d,lo,hi)  asm("mov.b64 %0, {%1, %2};"        : "=l"(d) : "f"(lo), "f"(hi))
#define UNPK2(lo,hi,v) asm("mov.b64 {%0, %1}, %2;"       : "=f"(lo), "=f"(hi) : "l"(v))
// fp16x2. PTX cvt.rn.f16x2.f32 d, a, b : a -> HIGH half, b -> LOW half.
#define HSUB2(d,a,b)   asm("sub.rn.f16x2 %0, %1, %2;"     : "=r"(d) : "r"(a), "r"(b))
#define HFMA2(d,a,b,c) asm("fma.rn.f16x2 %0, %1, %2, %3;" : "=r"(d) : "r"(a), "r"(b), "r"(c))
#define BCASTH(d,f)    asm("cvt.rn.f16x2.f32 %0, %1, %2;" : "=r"(d) : "f"(f), "f"(f))
#define PACKH(d,lo,hi) asm("cvt.rn.f16x2.f32 %0, %1, %2;" : "=r"(d) : "f"(hi), "f"(lo))
// half2 -> packed f32x2 (ull)
#define H2P2(d,v)      asm("{.reg .b16 l,h; .reg .f32 fl,fh; mov.b32 {l,h}, %1; " \
                           "cvt.f32.f16 fl, l; cvt.f32.f16 fh, h; mov.b64 %0, {fl, fh};}" \
                           : "=l"(d) : "r"(v))

__device__ int2 g_xrng[512];   // [band*128 + v*8 + yblk] = union {xmin, xmax}

__global__ void fp_zero_kernel(float4* __restrict__ out, int n4) {
    int i = blockIdx.x * blockDim.x + threadIdx.x;
    if (i < n4) out[i] = make_float4(0.f, 0.f, 0.f, 0.f);
}

// Per (band, view, y-block of 32): union of per-line active x ranges.
__global__ void fp_range_kernel() {
    int t = blockIdx.x * 256 + threadIdx.x;   // 0..511
    if (t >= 384) return;
    int b = t >> 7, v = (t >> 3) & 15, blk = t & 7;
    float unit = (float)(M_PI / 16.0);
    float mu   = (float)(M_PI / 180.0);
    float a = __fadd_rn(mu, __fmul_rn((float)v, unit));
    double da = (double)a;
    float c = (float)cos(da), s = (float)sin(da);   // s > 0 all views
    float inv_s = __fdividef(1.f, s);
    float inv_c = __fdividef(1.f, c);
    int mn = 256, mx = 0;
    for (int k = 0; k < 32; k++) {
        int y = (blk << 5) + k;
        float yf = (float)y - 127.5f;
        float A = fmaf(-s, yf, fmaf(-c, 127.5f, 127.5f));
        float B = fmaf( c, yf, fmaf(-s, 127.5f, 127.5f));
        float xa = (-1.f  - B) * inv_s;
        float xb = (256.f - B) * inv_s;
        float e0 = (-2.f  - A) * inv_c;
        float e1 = (258.f - A) * inv_c;
        float lo = fmaxf(xa, fminf(e0, e1));
        float hi = fminf(xb, fmaxf(e0, e1));
        int xlo = max(0,   (int)floorf(lo) - 2);
        int xhi = min(256, (int)ceilf(hi) + 3);
        if (xhi < xlo) xhi = xlo;
        int xbeg = xlo, xend = xhi;
        if (b > 0) {   // lower boundary: iy = 85b crossing
            float tb = (85.f * (float)b - B) * inv_s;
            tb = fminf(fmaxf(tb, -100000.f), 100000.f);
            xbeg = max(xlo, (int)floorf(tb) + 1 - 2);
        }
        if (b < 2) {   // upper boundary: iy = 85(b+1) crossing
            float tb = (85.f * (float)(b + 1) - B) * inv_s;
            tb = fminf(fmaxf(tb, -100000.f), 100000.f);
            xend = min(xhi, (int)floorf(tb) + 1 + 3);
        }
        if (xbeg < xend) { mn = min(mn, xbeg); mx = max(mx, xend); }
    }
    if (mn >= mx) { mn = 0; mx = 0; }
    g_xrng[t] = make_int2(mn, mx);
}

extern __shared__ uint tile[];   // [0,TOFF) = tileA (z0,z1); [TOFF,2*TOFF) = tileB

__global__ void __launch_bounds__(1024, 1)
fp_main_kernel(const float* __restrict__ vol, float* __restrict__ out)
{
    const int band = blockIdx.x >> 3;   // 0..2
    const int vg   = blockIdx.x & 7;    // view group of 2
    const int zq   = blockIdx.y;        // z-quad 0..63
    const int tid  = threadIdx.x;

    __shared__ float s_c[16], s_s[16], s_Ac[16], s_Bc[16];
    if (tid < 16) {
        float unit = (float)(M_PI / 16.0);
        float mu   = (float)(M_PI / 180.0);
        float a = __fadd_rn(mu, __fmul_rn((float)tid, unit));
        double da = (double)a;
        float c = (float)cos(da), s = (float)sin(da);
        s_c[tid] = c; s_s[tid] = s;
        s_Ac[tid] = fmaf(-c, 127.5f, 127.5f);
        s_Bc[tid] = fmaf(-s, 127.5f, 127.5f);
    }

    // zero both tiles, then overlay 86 vol rows at trow 4..89
    for (int i = tid; i < 2 * TOFF; i += 1024) tile[i] = 0u;
    __syncthreads();

    const int rbase = 85 * band;
    const float* __restrict__ v0 = vol + ((size_t)(zq << 2) << 16) + (rbase << 8);
    const float* __restrict__ v1 = v0 + 65536;
    const float* __restrict__ v2 = v0 + 2 * 65536;
    const float* __restrict__ v3 = v0 + 3 * 65536;
    for (int i = tid; i < 86 * 64; i += 1024) {
        int r = i >> 6, c4 = (i & 63) << 2;
        int off = (r << 8) + c4;
        float4 a = *(const float4*)(v0 + off);
        float4 b = *(const float4*)(v1 + off);
        float4 c = *(const float4*)(v2 + off);
        float4 d = *(const float4*)(v3 + off);
        uint* dA = &tile[(r + 4) * TS + 2 + c4];
        uint* dB = dA + TOFF;
        uint t;
        PACKH(t, a.x, b.x); dA[0] = t;  PACKH(t, c.x, d.x); dB[0] = t;
        PACKH(t, a.y, b.y); dA[1] = t;  PACKH(t, c.y, d.y); dB[1] = t;
        PACKH(t, a.z, b.z); dA[2] = t;  PACKH(t, c.z, d.z); dB[2] = t;
        PACKH(t, a.w, b.w); dA[3] = t;  PACKH(t, c.w, d.w); dB[3] = t;
    }
    __syncthreads();

    const int warp = tid >> 5, lane = tid & 31;
    const int v    = (vg << 1) + (warp >> 4);       // view
    const int yblk = (warp >> 1) & 7;
    const int h    = warp & 1;                      // x-half
    const int y    = (yblk << 5) + lane;

    // bit-domain clamps: tcol in [0,259], trow in [0,93]
    const int      LO_MIN = 0x4B400000 - 2,              LO_MAX = LO_MIN + 259;
    const int      HI_MIN = 0x4B400000 + 85 * band - 4,  HI_MAX = HI_MIN + 93;
    const unsigned UOFF   = (unsigned)HI_MIN * (unsigned)TS + (unsigned)LO_MIN;
    // ownership kill (trow window): b0 [0,88], b1 [4,88], b2 [4,93]
    const int      klo = (band == 0) ? 0 : 4;
    const int      khi = (band == 2) ? 93 : 88;
    const int      KB = HI_MIN + klo;
    const unsigned KS = (unsigned)(khi - klo);

    const ull MAGIC2  = 0x4B4000004B400000ULL;
    const ull NMAGIC2 = 0xCB400000CB400000ULL;
    const ull HALF2C  = 0x3F0000003F000000ULL;
    const ull NONE2   = 0xBF800000BF800000ULL;
    const ull STEP1   = 0x3F8000003F800000ULL;  // (1, 1)

    const float c = s_c[v], s = s_s[v];
    const float yf = (float)y - 127.5f;
    const float A = fmaf(-s, yf, s_Ac[v]) - 0.5f;
    const float B = fmaf( c, yf, s_Bc[v]) - 0.5f;
    ull cs2, ab2;
    PK2(cs2, c, s);
    PK2(ab2, A, B);

    int2 rng = __ldg(&g_xrng[(band << 7) + (v << 3) + yblk]);
    int xmin = rng.x, xmax = rng.y;
    // split union range between the two x-half warps
    const int mid = xmin + ((xmax - xmin + 1) >> 1);
    if (h) xmin = mid; else xmax = mid;
    if (xmin >= xmax) return;

    ull xf2, accP0 = 0ULL, accP1 = 0ULL;
    const float xm = (float)xmin;
    PK2(xf2, xm, xm);

    #pragma unroll 2
    for (int x = xmin; x < xmax; x++) {
        ull ih2, m2, f2, wh2, w2;
        FMA2(ih2, cs2, xf2, ab2);      // (ix-.5, iy-.5)
        ADD2(m2,  ih2, MAGIC2);
        ADD2(f2,  m2,  NMAGIC2);       // (floor ix, floor iy)
        FMA2(wh2, f2,  NONE2, ih2);
        ADD2(w2,  wh2, HALF2C);        // (wx, wy)
        int blo = (int)(unsigned)m2;
        int bhi = (int)(unsigned)(m2 >> 32);
        bool ok = ((unsigned)(bhi - KB) <= KS);    // ownership kill
        blo = min(max(blo, LO_MIN), LO_MAX);
        bhi = min(max(bhi, HI_MIN), HI_MAX);
        unsigned idx = (unsigned)bhi * (unsigned)TS + (unsigned)blo - UOFF;
        const uint* tA = &tile[idx];
        const uint* tB = tA + TOFF;
        uint A00 = tA[0], A01 = tA[1], A10 = tA[TS], A11 = tA[TS + 1];
        uint B00 = tB[0], B01 = tB[1], B10 = tB[TS], B11 = tB[TS + 1];
        float wx = __uint_as_float((unsigned)w2);
        float wy = __uint_as_float((unsigned)(w2 >> 32));
        uint WX, WY; BCASTH(WX, wx); BCASTH(WY, wy);
        uint D0, D1, H0, H1, DH, VALa, VALb;
        HSUB2(D0, A01, A00);
        HSUB2(D1, A11, A10);
        HFMA2(H0, WX, D0, A00);
        HFMA2(H1, WX, D1, A10);
        HSUB2(DH, H1, H0);
        HFMA2(VALa, WY, DH, H0);
        HSUB2(D0, B01, B00);
        HSUB2(D1, B11, B10);
        HFMA2(H0, WX, D0, B00);
        HFMA2(H1, WX, D1, B10);
        HSUB2(DH, H1, H0);
        HFMA2(VALb, WY, DH, H0);
        VALa = ok ? VALa : 0u;
        VALb = ok ? VALb : 0u;
        ull pa, pb;
        H2P2(pa, VALa); H2P2(pb, VALb);
        ADD2(accP0, accP0, pa);
        ADD2(accP1, accP1, pb);
        ADD2(xf2, xf2, STEP1);
    }

    float a0, a1, a2, a3;
    UNPK2(a0, a1, accP0);
    UNPK2(a2, a3, accP1);
    int oidx = ((((zq << 2) << 8) + y) << 4) + v;
    atomicAdd(&out[oidx],            a0);
    atomicAdd(&out[oidx +     4096], a1);
    atomicAdd(&out[oidx + 2 * 4096], a2);
    atomicAdd(&out[oidx + 3 * 4096], a3);
}

extern "C" void kernel_launch(void* const* d_in, const int* in_sizes, int n_in,
                              void* d_out, int out_size) {
    (void)in_sizes; (void)n_in;
    cudaFuncSetAttribute(fp_main_kernel,
                         cudaFuncAttributeMaxDynamicSharedMemorySize, TILE_BYTES);
    fp_zero_kernel<<<512, 512>>>((float4*)d_out, out_size / 4);
    fp_range_kernel<<<2, 256>>>();
    fp_main_kernel<<<dim3(24, 64), 1024, TILE_BYTES>>>((const float*)d_in[0], (float*)d_out);
}

// round 17
// speedup vs baseline: 1.0576x; 1.0529x over previous
#include <cuda_runtime.h>
#include <cuda_fp16.h>
#include <math.h>

#ifndef M_PI
#define M_PI 3.14159265358979323846
#endif

// z-pair half2 tile (lo=z0, hi=z1), TS=263 conflict-clean stride.
// LANE = Y-LINE with PER-LANE x ranges: each lane starts at its own xbeg and
// accumulates exactly len = xend-xbeg samples (i < len folded into the kill
// predicate — required because the hard x<=256 output cap is NOT covered by
// the geometric kills; see round-16 post-mortem). Warp iterates max(len).
//   p0 owns floor(iy) <= 127 (trow 0..129), p1 owns floor(iy) >= 128 (trow 5..133).
//   p0: vol rows 0..128 at trows 2..130; p1: vol rows 128..255 at trows 5..132.
//   cols: 0,1 zero | 2..257 data | 258..262 zero/pad
#define TS    263
#define TROWS 135
#define TILE_BYTES (TROWS * TS * 4)

typedef unsigned long long ull;
typedef unsigned int uint;

#define FMA2(d,a,b,c) asm("fma.rn.f32x2 %0, %1, %2, %3;" : "=l"(d) : "l"(a), "l"(b), "l"(c))
#define ADD2(d,a,b)   asm("add.rn.f32x2 %0, %1, %2;"     : "=l"(d) : "l"(a), "l"(b))
#define PK2(d,lo,hi)  asm("mov.b64 %0, {%1, %2};"        : "=l"(d) : "f"(lo), "f"(hi))
#define UNPK2(lo,hi,v) asm("mov.b64 {%0, %1}, %2;"       : "=f"(lo), "=f"(hi) : "l"(v))
// fp16x2. PTX cvt.rn.f16x2.f32 d, a, b : a -> HIGH half, b -> LOW half.
#define HSUB2(d,a,b)   asm("sub.rn.f16x2 %0, %1, %2;"     : "=r"(d) : "r"(a), "r"(b))
#define HFMA2(d,a,b,c) asm("fma.rn.f16x2 %0, %1, %2, %3;" : "=r"(d) : "r"(a), "r"(b), "r"(c))
#define BCASTH(d,f)    asm("cvt.rn.f16x2.f32 %0, %1, %2;" : "=r"(d) : "f"(f), "f"(f))
#define PACKH(d,lo,hi) asm("cvt.rn.f16x2.f32 %0, %1, %2;" : "=r"(d) : "f"(hi), "f"(lo))
// half2 -> packed f32x2 (ull)
#define H2P2(d,v)      asm("{.reg .b16 l,h; .reg .f32 fl,fh; mov.b32 {l,h}, %1; " \
                           "cvt.f32.f16 fl, l; cvt.f32.f16 fh, h; mov.b64 %0, {fl, fh};}" \
                           : "=l"(d) : "r"(v))
// integer warp max (u32 redux IS supported on sm_103; f32 is not)
#define REDUXMAX(d,s)  asm("redux.sync.max.u32 %0, %1, 0xffffffff;" : "=r"(d) : "r"(s))

__device__ int2 g_rng[8192];   // [(p<<12)|(v<<8)|y] = {xbeg, xend} per line

__global__ void fp_zero_kernel(float4* __restrict__ out, int n4) {
    int i = blockIdx.x * blockDim.x + threadIdx.x;
    if (i < n4) out[i] = make_float4(0.f, 0.f, 0.f, 0.f);
}

// Per (phase, view, y): this line's active x range (round-13 logic, un-unioned).
__global__ void fp_range_kernel() {
    int t = blockIdx.x * 256 + threadIdx.x;   // 0..8191
    int p = t >> 12, v = (t >> 8) & 15, y = t & 255;
    float unit = (float)(M_PI / 16.0);
    float mu   = (float)(M_PI / 180.0);
    float a = __fadd_rn(mu, __fmul_rn((float)v, unit));
    double da = (double)a;
    float c = (float)cos(da), s = (float)sin(da);   // s > 0 all views
    float inv_s = __fdividef(1.f, s);
    float inv_c = __fdividef(1.f, c);
    float yf = (float)y - 127.5f;
    float A = fmaf(-s, yf, fmaf(-c, 127.5f, 127.5f));
    float B = fmaf( c, yf, fmaf(-s, 127.5f, 127.5f));
    float xa = (-1.f  - B) * inv_s;
    float xb = (256.f - B) * inv_s;
    float e0 = (-2.f  - A) * inv_c;
    float e1 = (258.f - A) * inv_c;
    float lo = fmaxf(xa, fminf(e0, e1));
    float hi = fminf(xb, fmaxf(e0, e1));
    int xlo = max(0,   (int)floorf(lo) - 2);
    int xhi = min(256, (int)ceilf(hi) + 3);
    if (xhi < xlo) xhi = xlo;
    // iy = 128.0 crossing: ownership boundary (floor(iy) 127 vs 128)
    float t128f = (128.f - B) * inv_s;
    t128f = fminf(fmaxf(t128f, -100000.f), 100000.f);
    int t128 = (int)floorf(t128f);
    int xbeg, xend;
    if (p == 0) { xbeg = xlo;                xend = min(xhi, t128 + 3); }
    else        { xbeg = max(xlo, t128 - 2); xend = xhi; }
    if (xend < xbeg) xend = xbeg;
    g_rng[t] = make_int2(xbeg, xend);
}

extern __shared__ uint tile[];   // half2 per element

__global__ void __launch_bounds__(1024, 1)
fp_main_kernel(const float* __restrict__ vol, float* __restrict__ out)
{
    const int bx  = blockIdx.x;
    const int zp  = bx >> 3;          // z-pair 0..127
    const int p   = (bx >> 2) & 1;    // row-half phase
    const int vg  = bx & 3;           // view group of 4
    const int tid = threadIdx.x;

    __shared__ float s_c[16], s_s[16], s_Ac[16], s_Bc[16];
    if (tid < 16) {
        float unit = (float)(M_PI / 16.0);
        float mu   = (float)(M_PI / 180.0);
        float a = __fadd_rn(mu, __fmul_rn((float)tid, unit));
        double da = (double)a;
        float c = (float)cos(da), s = (float)sin(da);
        s_c[tid] = c; s_s[tid] = s;
        s_Ac[tid] = fmaf(-c, 127.5f, 127.5f);
        s_Bc[tid] = fmaf(-s, 127.5f, 127.5f);
    }

    // zero whole tile, then overlay data rows
    for (int i = tid; i < TROWS * TS; i += 1024) tile[i] = 0u;
    __syncthreads();

    const int r0     = p ? 128 : 0;   // first vol row in tile
    const int rowoff = p ? 5   : 2;   // its tile row
    const int nrows  = p ? 128 : 129;
    const float* __restrict__ v0 = vol + ((size_t)(zp << 1) << 16) + (r0 << 8);
    const float* __restrict__ v1 = v0 + 65536;
    for (int i = tid; i < nrows * 64; i += 1024) {
        int r = i >> 6, c4 = (i & 63) << 2;
        int off = (r << 8) + c4;
        float4 a = *(const float4*)(v0 + off);
        float4 b = *(const float4*)(v1 + off);
        uint* d = &tile[(r + rowoff) * TS + 2 + c4];
        uint t;
        PACKH(t, a.x, b.x); d[0] = t;
        PACKH(t, a.y, b.y); d[1] = t;
        PACKH(t, a.z, b.z); d[2] = t;
        PACKH(t, a.w, b.w); d[3] = t;
    }
    __syncthreads();

    const int warp = tid >> 5, lane = tid & 31;
    const int v    = (vg << 2) + (warp >> 3);   // this warp's view
    const int yblk = warp & 7;
    const int y    = (yblk << 5) + lane;        // this lane's output line

    // bit-domain clamps: tcol in [0,259], trow in [0,133]
    const int      LO_MIN = 0x4B400000 - 2,               LO_MAX = LO_MIN + 259;
    const int      HI_MIN = 0x4B400000 + (p ? 123 : -2),  HI_MAX = HI_MIN + 133;
    const unsigned UOFF   = (unsigned)HI_MIN * (unsigned)TS + (unsigned)LO_MIN;
    // ownership kill: p0 valid trow 0..129 (floor <= 127); p1 trow 5..133 (floor >= 128)
    const int      KB = HI_MIN + (p ? 5 : 0);
    const unsigned KS = p ? 128u : 129u;

    const ull MAGIC2  = 0x4B4000004B400000ULL;
    const ull NMAGIC2 = 0xCB400000CB400000ULL;
    const ull HALF2C  = 0x3F0000003F000000ULL;
    const ull NONE2   = 0xBF800000BF800000ULL;
    const ull STEP1   = 0x3F8000003F800000ULL;  // (1, 1)

    const float c = s_c[v], s = s_s[v];
    const float yf = (float)y - 127.5f;
    const float A = fmaf(-s, yf, s_Ac[v]) - 0.5f;   // ix-0.5 = c*x + A
    const float B = fmaf( c, yf, s_Bc[v]) - 0.5f;   // iy-0.5 = s*x + B
    ull cs2, ab2;
    PK2(cs2, c, s);
    PK2(ab2, A, B);

    // per-lane range (coalesced: consecutive y per lane)
    int2 rr = __ldg(&g_rng[(p << 12) + (v << 8) + y]);
    const uint len = (uint)(rr.y - rr.x);
    uint L; REDUXMAX(L, len);
    if (L == 0u) return;

    ull xf2, acc = 0ULL;
    const float xm = (float)rr.x;     // per-lane start
    PK2(xf2, xm, xm);

    #pragma unroll 4
    for (uint i = 0; i < L; i++) {
        ull ih2, m2, f2, wh2, w2;
        FMA2(ih2, cs2, xf2, ab2);      // (ix-.5, iy-.5)
        ADD2(m2,  ih2, MAGIC2);
        ADD2(f2,  m2,  NMAGIC2);       // (floor ix, floor iy)
        FMA2(wh2, f2,  NONE2, ih2);
        ADD2(w2,  wh2, HALF2C);        // (wx, wy)
        int blo = (int)(unsigned)m2;
        int bhi = (int)(unsigned)(m2 >> 32);
        // ownership kill AND per-lane trip mask (covers the hard x<256 cap)
        bool ok = ((unsigned)(bhi - KB) <= KS) & (i < len);
        blo = min(max(blo, LO_MIN), LO_MAX);
        bhi = min(max(bhi, HI_MIN), HI_MAX);
        unsigned idx = (unsigned)bhi * (unsigned)TS + (unsigned)blo - UOFF;
        const uint* tp = &tile[idx];
        uint V00 = tp[0], V01 = tp[1], V10 = tp[TS], V11 = tp[TS + 1];
        float wx = __uint_as_float((unsigned)w2);
        float wy = __uint_as_float((unsigned)(w2 >> 32));
        uint WX, WY; BCASTH(WX, wx); BCASTH(WY, wy);
        uint D0, D1, H0, H1, DH, VAL;
        HSUB2(D0, V01, V00);
        HSUB2(D1, V11, V10);
        HFMA2(H0, WX, D0, V00);
        HFMA2(H1, WX, D1, V10);
        HSUB2(DH, H1, H0);
        HFMA2(VAL, WY, DH, H0);
        VAL = ok ? VAL : 0u;
        ull pv; H2P2(pv, VAL);
        ADD2(acc, acc, pv);
        ADD2(xf2, xf2, STEP1);
    }

    float a0, a1;
    UNPK2(a0, a1, acc);
    int oidx = ((((zp << 1) << 8) + y) << 4) + v;
    atomicAdd(&out[oidx],        a0);
    atomicAdd(&out[oidx + 4096], a1);
}

extern "C" void kernel_launch(void* const* d_in, const int* in_sizes, int n_in,
                              void* d_out, int out_size) {
    (void)in_sizes; (void)n_in;
    cudaFuncSetAttribute(fp_main_kernel,
                         cudaFuncAttributeMaxDynamicSharedMemorySize, TILE_BYTES);
    fp_zero_kernel<<<512, 512>>>((float4*)d_out, out_size / 4);
    fp_range_kernel<<<32, 256>>>();
    fp_main_kernel<<<1024, 1024, TILE_BYTES>>>((const float*)d_in[0], (float*)d_out);
}